// round 4
// baseline (speedup 1.0000x reference)
#include <cuda_runtime.h>
#include <cuda_bf16.h>
#include <math.h>

// GCN_57449482551753: 2-layer GCN
//   inputs: x[100000,128] f32, edge_index[2,1600000] (int64 OR int32, detected),
//           W1[128,128], b1[128], W2[128,16], b2[16]
//   output: concat(logits[100000,16], log_softmax[100000,16]) f32 (size-guarded)

#define NN 100000
#define FD 128
#define CD 16

// ---------------- device scratch (static, allocation-free) ----------------
__device__ __align__(16) float g_deg [NN];          // degree -> dinv (in place)
__device__ __align__(16) float g_hs  [NN * FD];     // dinv*h (layer1 msgs); reused as h2
__device__ __align__(16) float g_acc1[NN * FD];     // layer1 accumulator
__device__ __align__(16) float g_gs  [NN * CD];     // dinv*(h2@W2) (layer2 msgs)
__device__ __align__(16) float g_acc2[NN * CD];     // layer2 accumulator
__device__ int g_is64;

// ---------------- helpers ----------------
__device__ __forceinline__ int edge_at(const void* e, int i, int is64) {
    if (is64) return (int)(((const long long*)e)[i]);
    return ((const int*)e)[i];
}

__device__ __forceinline__ void red_add_v4(float* addr, float4 v) {
    asm volatile("red.global.add.v4.f32 [%0], {%1,%2,%3,%4};"
                 :: "l"(addr), "f"(v.x), "f"(v.y), "f"(v.z), "f"(v.w)
                 : "memory");
}

// ---------------- kernels ----------------

// init: deg = 1 (self loop), detect edge dtype
__global__ void k_init(const void* eidx) {
    int i = blockIdx.x * blockDim.x + threadIdx.x;
    if (i < NN) g_deg[i] = 1.0f;
    if (i == 0) {
        const int* p = (const int*)eidx;
        int all0 = 1;
        #pragma unroll
        for (int j = 0; j < 64; j++)
            if (p[2 * j + 1] != 0) all0 = 0;   // int64 hi-words are 0 for idx < 2^31
        g_is64 = all0;
    }
}

// degree count over dst
__global__ void k_deg(const void* eidx, int E) {
    int i = blockIdx.x * blockDim.x + threadIdx.x;
    if (i >= E) return;
    int is64 = g_is64;
    int d = edge_at(eidx, i + E, is64);
    atomicAdd(&g_deg[d], 1.0f);
}

// deg -> dinv
__global__ void k_dinv() {
    int i = blockIdx.x * blockDim.x + threadIdx.x;
    if (i < NN) g_deg[i] = rsqrtf(g_deg[i]);
}

// hs = dinv[row] * (x @ W1); also acc1 = hs (self-loop init).
// block: 256 threads, 32-row tile, 4x4 register blocking, K split in 2 chunks.
__global__ void k_gemm1(const float* __restrict__ x, const float* __restrict__ W1) {
    __shared__ float ws[64 * 128];  // 32 KB
    __shared__ float xs[32 * 64];   //  8 KB
    int t  = threadIdx.x;
    int tx = t & 31, ty = t >> 5;   // ty = warp id (0..7), 4 rows each
    int row0 = blockIdx.x * 32;
    float acc[4][4] = {};

    for (int kb = 0; kb < 2; kb++) {
        const float4* Wsrc = (const float4*)(W1 + kb * 64 * 128);
        float4* Wdst = (float4*)ws;
        #pragma unroll
        for (int i = t; i < 2048; i += 256) Wdst[i] = Wsrc[i];
        for (int i = t; i < 512; i += 256) {
            int r = i >> 4, kk = i & 15;   // 16 float4 per 64-wide row
            ((float4*)xs)[r * 16 + kk] =
                ((const float4*)(x + (size_t)(row0 + r) * 128 + kb * 64))[kk];
        }
        __syncthreads();
        #pragma unroll 8
        for (int k = 0; k < 64; k++) {
            float xv[4], wv[4];
            #pragma unroll
            for (int i = 0; i < 4; i++) xv[i] = xs[(ty * 4 + i) * 64 + k];  // broadcast
            #pragma unroll
            for (int j = 0; j < 4; j++) wv[j] = ws[k * 128 + tx + 32 * j];  // conflict-free
            #pragma unroll
            for (int i = 0; i < 4; i++)
                #pragma unroll
                for (int j = 0; j < 4; j++)
                    acc[i][j] += xv[i] * wv[j];
        }
        __syncthreads();
    }
    #pragma unroll
    for (int i = 0; i < 4; i++) {
        int r = row0 + ty * 4 + i;
        float dv = g_deg[r];
        #pragma unroll
        for (int j = 0; j < 4; j++) {
            float v = acc[i][j] * dv;
            int idx = r * 128 + tx + 32 * j;
            g_hs[idx]   = v;
            g_acc1[idx] = v;
        }
    }
}

// scatter layer 1: one warp per edge, 32 lanes x float4 vector-RED
__global__ void k_scatter1(const void* __restrict__ eidx, int E) {
    int warp = (blockIdx.x * blockDim.x + threadIdx.x) >> 5;
    int lane = threadIdx.x & 31;
    if (warp >= E) return;
    int is64 = g_is64;
    int s = edge_at(eidx, warp, is64);
    int d = edge_at(eidx, warp + E, is64);
    float4 v = ((const float4*)g_hs)[s * 32 + lane];
    red_add_v4(g_acc1 + d * 128 + lane * 4, v);
}

// h2 = relu(dinv * acc1 + b1), written over g_hs
__global__ void k_h2(const float* __restrict__ b1) {
    int i = blockIdx.x * blockDim.x + threadIdx.x;  // over NN*32 float4
    if (i >= NN * 32) return;
    int node = i >> 5, q = i & 31;
    float dv = g_deg[node];
    float4 a  = ((const float4*)g_acc1)[i];
    float4 bb = ((const float4*)b1)[q];
    float4 r;
    r.x = fmaxf(fmaf(a.x, dv, bb.x), 0.f);
    r.y = fmaxf(fmaf(a.y, dv, bb.y), 0.f);
    r.z = fmaxf(fmaf(a.z, dv, bb.z), 0.f);
    r.w = fmaxf(fmaf(a.w, dv, bb.w), 0.f);
    ((float4*)g_hs)[i] = r;
}

// gs = dinv * (h2 @ W2); acc2 = gs. 128 threads = 8 nodes x 16 cols.
__global__ void k_gemm2(const float* __restrict__ W2) {
    __shared__ float w2s[128 * 16];  // [k][c], 8 KB
    __shared__ float h2s[8][128];
    int t = threadIdx.x;
    for (int i = t; i < 2048; i += 128) w2s[i] = W2[i];
    int n0 = blockIdx.x * 8;
    for (int i = t; i < 1024; i += 128) {
        int r = i >> 7, k = i & 127;
        h2s[r][k] = g_hs[(size_t)(n0 + r) * 128 + k];
    }
    __syncthreads();
    int nl = t >> 4, c = t & 15;
    int node = n0 + nl;
    float s = 0.f;
    #pragma unroll 8
    for (int k = 0; k < 128; k++) s += h2s[nl][k] * w2s[k * 16 + c];
    float v = s * g_deg[node];
    g_gs[node * 16 + c]   = v;
    g_acc2[node * 16 + c] = v;
}

// scatter layer 2: thread per (edge, float4-quad)
__global__ void k_scatter2(const void* __restrict__ eidx, int E) {
    int i = blockIdx.x * blockDim.x + threadIdx.x;
    if (i >= E * 4) return;
    int e = i >> 2, q = i & 3;
    int is64 = g_is64;
    int s = edge_at(eidx, e, is64);
    int d = edge_at(eidx, e + E, is64);
    float4 v = ((const float4*)g_gs)[s * 4 + q];
    red_add_v4(g_acc2 + d * 16 + q * 4, v);
}

// logits = dinv*acc2 + b2; write [logits | log_softmax] (size-guarded)
__global__ void k_final(const float* __restrict__ b2, float* __restrict__ out,
                        long long out_size) {
    int n = blockIdx.x * blockDim.x + threadIdx.x;
    if (n >= NN) return;
    float dv = g_deg[n];
    float lg[16];
    float mx = -INFINITY;
    #pragma unroll
    for (int c = 0; c < 16; c++) {
        lg[c] = fmaf(g_acc2[n * 16 + c], dv, b2[c]);
        mx = fmaxf(mx, lg[c]);
    }
    float sum = 0.f;
    #pragma unroll
    for (int c = 0; c < 16; c++) sum += expf(lg[c] - mx);
    float lse = logf(sum) + mx;

    long long base = (long long)n * 16;
    if (base + 16 <= out_size) {
        #pragma unroll
        for (int c = 0; c < 16; c++) out[base + c] = lg[c];
    }
    long long base2 = (long long)NN * 16 + base;
    if (base2 + 16 <= out_size) {
        #pragma unroll
        for (int c = 0; c < 16; c++) out[base2 + c] = lg[c] - lse;
    }
}

// ---------------- launch ----------------
extern "C" void kernel_launch(void* const* d_in, const int* in_sizes, int n_in,
                              void* d_out, int out_size) {
    const float* x   = (const float*)d_in[0];
    const void*  eix = d_in[1];                 // int64 or int32, detected on device
    const float* W1  = (const float*)d_in[2];
    const float* b1  = (const float*)d_in[3];
    const float* W2  = (const float*)d_in[4];
    const float* b2  = (const float*)d_in[5];
    float* out = (float*)d_out;

    int E = in_sizes[1] / 2;                    // 1,600,000

    k_init<<<(NN + 255) / 256, 256>>>(eix);
    k_deg<<<(E + 255) / 256, 256>>>(eix, E);
    k_dinv<<<(NN + 255) / 256, 256>>>();
    k_gemm1<<<NN / 32, 256>>>(x, W1);
    {
        long long thr = (long long)E * 32;
        k_scatter1<<<(unsigned)((thr + 255) / 256), 256>>>(eix, E);
    }
    k_h2<<<(NN * 32 + 255) / 256, 256>>>(b1);
    k_gemm2<<<NN / 8, 128>>>(W2);
    k_scatter2<<<(E * 4 + 255) / 256, 256>>>(eix, E);
    k_final<<<(NN + 255) / 256, 256>>>(b2, out, (long long)out_size);
}

// round 7
// speedup vs baseline: 1.5935x; 1.5935x over previous
#include <cuda_runtime.h>
#include <cuda_bf16.h>
#include <math.h>

// GCN_57449482551753: 2-layer GCN, sort-based aggregation (no feature atomics)
//   inputs: x[100000,128] f32, edge_index[2,1600000] (int64 OR int32, detected),
//           W1[128,128], b1[128], W2[128,16], b2[16]
//   output: concat(logits[100000,16], log_softmax[100000,16]) f32 (size-guarded)

#define NN 100000
#define FD 128
#define CD 16
#define SCAN_BLK 1024
#define N_SCAN_BLKS ((NN + SCAN_BLK - 1) / SCAN_BLK)   // 98
#define EMAX 1700000

// ---------------- device scratch (static, allocation-free) ----------------
__device__ __align__(16) float g_hs  [NN * FD];     // dinv*(x@W1)  (layer-1 msgs)
__device__ __align__(16) float g_h2  [NN * FD];     // relu layer-1 output
__device__ __align__(16) float g_gs  [NN * CD];     // dinv*(h2@W2) (layer-2 msgs)
__device__ float g_dinv[NN];
__device__ int   g_hist[NN];
__device__ int   g_row [NN + 1];
__device__ int   g_cur [NN];
__device__ int   g_bsum[N_SCAN_BLKS];
__device__ int   g_boff[N_SCAN_BLKS];
__device__ int   g_ssrc[EMAX];                      // src grouped by dst (CSR)
__device__ int   g_is64;

// ---------------- helpers ----------------
__device__ __forceinline__ int edge_at(const void* e, int i, int is64) {
    if (is64) return (int)(((const long long*)e)[i]);
    return ((const int*)e)[i];
}

// ---------------- kernels ----------------

// zero histogram + detect edge dtype
__global__ void k_init0(const void* eidx) {
    int i = blockIdx.x * blockDim.x + threadIdx.x;
    if (i < NN) g_hist[i] = 0;
    if (i == 0) {
        const int* p = (const int*)eidx;
        int all0 = 1;
        #pragma unroll
        for (int j = 0; j < 64; j++)
            if (p[2 * j + 1] != 0) all0 = 0;   // int64 hi-words are 0 for idx < 2^31
        g_is64 = all0;
    }
}

// histogram over dst
__global__ void k_hist(const void* __restrict__ eidx, int E) {
    int i = blockIdx.x * blockDim.x + threadIdx.x;
    if (i >= E) return;
    int d = edge_at(eidx, i + E, g_is64);
    atomicAdd(&g_hist[d], 1);
}

// block-level inclusive scan (Hillis-Steele), emits block-local exclusive + block sums
__global__ void k_scan1() {
    __shared__ int s[SCAN_BLK];
    int t = threadIdx.x;
    int i = blockIdx.x * SCAN_BLK + t;
    int v = (i < NN) ? g_hist[i] : 0;
    int x = v;
    s[t] = x;
    __syncthreads();
    #pragma unroll
    for (int o = 1; o < SCAN_BLK; o <<= 1) {
        int tmp = (t >= o) ? s[t - o] : 0;
        __syncthreads();
        x += tmp;
        s[t] = x;
        __syncthreads();
    }
    if (i < NN) g_row[i] = x - v;               // block-local exclusive
    if (t == SCAN_BLK - 1) g_bsum[blockIdx.x] = x;
}

// serial scan of 98 block sums
__global__ void k_scan2() {
    if (threadIdx.x == 0 && blockIdx.x == 0) {
        int run = 0;
        for (int b = 0; b < N_SCAN_BLKS; b++) {
            g_boff[b] = run;
            run += g_bsum[b];
        }
    }
}

// finalize row offsets, cursors, dinv
__global__ void k_scan3(int E) {
    int i = blockIdx.x * blockDim.x + threadIdx.x;
    if (i < NN) {
        int rs = g_row[i] + g_boff[i >> 10];
        g_row[i] = rs;
        g_cur[i] = rs;
        g_dinv[i] = rsqrtf((float)(g_hist[i] + 1));   // +1 self loop
    } else if (i == NN) {
        g_row[NN] = E;
    }
}

// counting-sort scatter: src indices grouped by dst
__global__ void k_sort(const void* __restrict__ eidx, int E) {
    int i = blockIdx.x * blockDim.x + threadIdx.x;
    if (i >= E) return;
    int is64 = g_is64;
    int s = edge_at(eidx, i, is64);
    int d = edge_at(eidx, i + E, is64);
    int pos = atomicAdd(&g_cur[d], 1);
    g_ssrc[pos] = s;
}

// hs = dinv[row] * (x @ W1). 64-row tile, 256 threads, 8x4 register blocking.
__global__ void __launch_bounds__(256) k_gemm1(const float* __restrict__ x,
                                               const float* __restrict__ W1) {
    __shared__ float ws[32 * 128];  // [k][c] chunk, 16 KB
    __shared__ float xs[64 * 32];   // [r][k] chunk,  8 KB
    int t  = threadIdx.x;
    int tx = t & 31, ty = t >> 5;                  // tx -> 4 contiguous cols, ty -> 8 rows
    int row0 = blockIdx.x * 64;
    float acc[8][4] = {};

    for (int kb = 0; kb < 4; kb++) {
        const float4* Wsrc = (const float4*)(W1 + kb * 32 * 128);
        #pragma unroll
        for (int i = t; i < 1024; i += 256) ((float4*)ws)[i] = Wsrc[i];
        #pragma unroll
        for (int i = t; i < 512; i += 256) {
            int r = i >> 3, kk = i & 7;
            int gr = row0 + r; if (gr >= NN) gr = NN - 1;
            ((float4*)xs)[r * 8 + kk] =
                ((const float4*)(x + (size_t)gr * 128 + kb * 32))[kk];
        }
        __syncthreads();
        #pragma unroll 8
        for (int k = 0; k < 32; k++) {
            float4 wv = ((const float4*)ws)[k * 32 + tx];
            float xv[8];
            #pragma unroll
            for (int i = 0; i < 8; i++) xv[i] = xs[(ty * 8 + i) * 32 + k];  // broadcast
            #pragma unroll
            for (int i = 0; i < 8; i++) {
                acc[i][0] = fmaf(xv[i], wv.x, acc[i][0]);
                acc[i][1] = fmaf(xv[i], wv.y, acc[i][1]);
                acc[i][2] = fmaf(xv[i], wv.z, acc[i][2]);
                acc[i][3] = fmaf(xv[i], wv.w, acc[i][3]);
            }
        }
        __syncthreads();
    }
    #pragma unroll
    for (int i = 0; i < 8; i++) {
        int r = row0 + ty * 8 + i;
        if (r < NN) {
            float dv = g_dinv[r];
            float4 v;
            v.x = acc[i][0] * dv; v.y = acc[i][1] * dv;
            v.z = acc[i][2] * dv; v.w = acc[i][3] * dv;
            ((float4*)g_hs)[(size_t)r * 32 + tx] = v;
        }
    }
}

// layer-1 aggregation: warp per dst node, CSR, register accumulation,
// fused self-loop + dinv + bias + relu epilogue.
__global__ void k_agg1(const float* __restrict__ b1) {
    int warp = (blockIdx.x * blockDim.x + threadIdx.x) >> 5;
    int lane = threadIdx.x & 31;
    if (warp >= NN) return;
    int beg = g_row[warp], end = g_row[warp + 1];
    const float4* hs4 = (const float4*)g_hs;
    float4 acc = hs4[(size_t)warp * 32 + lane];    // self loop
    int e = beg;
    for (; e + 4 <= end; e += 4) {
        int s0 = g_ssrc[e], s1 = g_ssrc[e + 1], s2 = g_ssrc[e + 2], s3 = g_ssrc[e + 3];
        float4 a = hs4[(size_t)s0 * 32 + lane];
        float4 b = hs4[(size_t)s1 * 32 + lane];
        float4 c = hs4[(size_t)s2 * 32 + lane];
        float4 d = hs4[(size_t)s3 * 32 + lane];
        acc.x += (a.x + b.x) + (c.x + d.x);
        acc.y += (a.y + b.y) + (c.y + d.y);
        acc.z += (a.z + b.z) + (c.z + d.z);
        acc.w += (a.w + b.w) + (c.w + d.w);
    }
    for (; e < end; e++) {
        int s = g_ssrc[e];
        float4 a = hs4[(size_t)s * 32 + lane];
        acc.x += a.x; acc.y += a.y; acc.z += a.z; acc.w += a.w;
    }
    float dv = g_dinv[warp];
    float4 bb = ((const float4*)b1)[lane];
    float4 r;
    r.x = fmaxf(fmaf(acc.x, dv, bb.x), 0.f);
    r.y = fmaxf(fmaf(acc.y, dv, bb.y), 0.f);
    r.z = fmaxf(fmaf(acc.z, dv, bb.z), 0.f);
    r.w = fmaxf(fmaf(acc.w, dv, bb.w), 0.f);
    ((float4*)g_h2)[(size_t)warp * 32 + lane] = r;
}

// gs = dinv * (h2 @ W2). 128 threads = 8 nodes x 16 cols.
__global__ void k_gemm2(const float* __restrict__ W2) {
    __shared__ float w2s[128 * 16];
    __shared__ float h2s[8][128];
    int t = threadIdx.x;
    for (int i = t; i < 2048; i += 128) w2s[i] = W2[i];
    int n0 = blockIdx.x * 8;
    for (int i = t; i < 1024; i += 128) {
        int r = i >> 7, k = i & 127;
        h2s[r][k] = g_h2[(size_t)(n0 + r) * 128 + k];
    }
    __syncthreads();
    int nl = t >> 4, c = t & 15;
    int node = n0 + nl;
    float s = 0.f;
    #pragma unroll 8
    for (int k = 0; k < 128; k++) s = fmaf(h2s[nl][k], w2s[k * 16 + c], s);
    g_gs[(size_t)node * 16 + c] = s * g_dinv[node];
}

// layer-2 aggregation fused with bias + log_softmax + output write.
// Warp per node: lanes split into 2 halves of 16, each half strides edges by 2.
__global__ void k_agg2(const float* __restrict__ b2, float* __restrict__ out,
                       long long out_size) {
    int warp = (blockIdx.x * blockDim.x + threadIdx.x) >> 5;
    int lane = threadIdx.x & 31;
    if (warp >= NN) return;
    int c = lane & 15, half = lane >> 4;
    int beg = g_row[warp], end = g_row[warp + 1];
    float acc = half ? 0.f : g_gs[(size_t)warp * 16 + c];   // self loop in half 0
    for (int e = beg + half; e < end; e += 2)
        acc += g_gs[(size_t)g_ssrc[e] * 16 + c];
    acc += __shfl_xor_sync(0xffffffffu, acc, 16);           // merge halves

    float lg = fmaf(acc, g_dinv[warp], b2[c]);
    float mx = lg;
    #pragma unroll
    for (int o = 8; o; o >>= 1) mx = fmaxf(mx, __shfl_xor_sync(0xffffffffu, mx, o));
    float sum = expf(lg - mx);
    #pragma unroll
    for (int o = 8; o; o >>= 1) sum += __shfl_xor_sync(0xffffffffu, sum, o);
    float ls = lg - (logf(sum) + mx);

    if (half == 0) {
        long long base = (long long)warp * 16;
        if (base + 16 <= out_size) out[base + c] = lg;
        long long base2 = (long long)NN * 16 + base;
        if (base2 + 16 <= out_size) out[base2 + c] = ls;
    }
}

// ---------------- launch ----------------
extern "C" void kernel_launch(void* const* d_in, const int* in_sizes, int n_in,
                              void* d_out, int out_size) {
    const float* x   = (const float*)d_in[0];
    const void*  eix = d_in[1];                 // int64 or int32, detected on device
    const float* W1  = (const float*)d_in[2];
    const float* b1  = (const float*)d_in[3];
    const float* W2  = (const float*)d_in[4];
    const float* b2  = (const float*)d_in[5];
    float* out = (float*)d_out;

    int E = in_sizes[1] / 2;                    // 1,600,000

    k_init0<<<(NN + 255) / 256, 256>>>(eix);
    k_hist <<<(E + 255) / 256, 256>>>(eix, E);
    k_scan1<<<N_SCAN_BLKS, SCAN_BLK>>>();
    k_scan2<<<1, 32>>>();
    k_scan3<<<(NN + 1 + 255) / 256, 256>>>(E);
    k_sort <<<(E + 255) / 256, 256>>>(eix, E);
    k_gemm1<<<(NN + 63) / 64, 256>>>(x, W1);
    k_agg1 <<<(NN * 32 + 255) / 256, 256>>>(b1);           // 12500 blocks
    k_gemm2<<<NN / 8, 128>>>(W2);
    k_agg2 <<<(NN * 32 + 255) / 256, 256>>>(b2, out, (long long)out_size);
}